// round 1
// baseline (speedup 1.0000x reference)
#include <cuda_runtime.h>

#define N_   4
#define L_   4096
#define H_   8
#define D_   64
#define NH   32
#define EPSF 1e-6f

#define CHUNK 256   // tokens per pass1 CTA
#define SUBT  32    // tokens per smem sub-tile
#define TL    64    // tokens per pass2 CTA

// Scratch (allocation-free rule: device globals)
__device__ float g_KV[NH][D_ * D_];   // [nh][d*64 + m]
__device__ float g_Ksum[NH][D_];

__device__ __forceinline__ float fmap(float x) {
    // elu(x) + 1
    return x > 0.f ? x + 1.f : __expf(x);
}

__global__ void zero_kernel() {
    int idx = blockIdx.x * blockDim.x + threadIdx.x;
    if (idx < NH * D_ * D_) ((float*)g_KV)[idx] = 0.f;
    if (idx < NH * D_)      ((float*)g_Ksum)[idx] = 0.f;
}

// Pass 1: KV[d][m] += fmap(k)[l,d] * v[l,m]; Ksum[d] += fmap(k)[l,d]
__global__ __launch_bounds__(256) void pass1(const float* __restrict__ keys,
                                             const float* __restrict__ values) {
    __shared__ float ks[SUBT][D_];
    __shared__ float vs[SUBT][D_];

    const int nh    = blockIdx.x;          // 0..31
    const int chunk = blockIdx.y;          // 0..15
    const int n = nh >> 3, h = nh & 7;
    const int tid  = threadIdx.x;
    const int dblk = tid >> 4;             // 0..15 -> d rows [dblk*4, dblk*4+3]
    const int mblk = tid & 15;             // 0..15 -> m cols [mblk*4, mblk*4+3]

    const float* kbase = keys   + ((size_t)(n * L_) * H_ + h) * D_;
    const float* vbase = values + ((size_t)(n * L_) * H_ + h) * D_;
    const int l0 = chunk * CHUNK;

    float acc[4][4] = {};
    float ksum[4]   = {};

    for (int sub = 0; sub < CHUNK / SUBT; ++sub) {
        const int lbase = l0 + sub * SUBT;
        // cooperative load: 32 tokens x 64 floats for k and v
        #pragma unroll
        for (int r = 0; r < 2; ++r) {
            int f = r * 256 + tid;
            int t = f >> 4;        // token within sub-tile
            int q = f & 15;        // float4 quad within row
            size_t row = (size_t)(lbase + t) * (H_ * D_);
            float4 kk = ((const float4*)(kbase + row))[q];
            kk.x = fmap(kk.x); kk.y = fmap(kk.y); kk.z = fmap(kk.z); kk.w = fmap(kk.w);
            *(float4*)&ks[t][q * 4] = kk;
            *(float4*)&vs[t][q * 4] = ((const float4*)(vbase + row))[q];
        }
        __syncthreads();

        #pragma unroll 8
        for (int t = 0; t < SUBT; ++t) {
            float4 kk = *(float4*)&ks[t][dblk * 4];
            float4 vv = *(float4*)&vs[t][mblk * 4];
            float kr[4] = {kk.x, kk.y, kk.z, kk.w};
            float vr[4] = {vv.x, vv.y, vv.z, vv.w};
            #pragma unroll
            for (int i = 0; i < 4; ++i) {
                ksum[i] += kr[i];
                #pragma unroll
                for (int j = 0; j < 4; ++j)
                    acc[i][j] += kr[i] * vr[j];
            }
        }
        __syncthreads();
    }

    float* kvout = g_KV[nh];
    #pragma unroll
    for (int i = 0; i < 4; ++i)
        #pragma unroll
        for (int j = 0; j < 4; ++j)
            atomicAdd(&kvout[(dblk * 4 + i) * D_ + mblk * 4 + j], acc[i][j]);

    if (mblk == 0) {
        #pragma unroll
        for (int i = 0; i < 4; ++i)
            atomicAdd(&g_Ksum[nh][dblk * 4 + i], ksum[i]);
    }
}

// Pass 2: out[l][m] = z_l * sum_d fmap(q)[l,d] * KV[d][m]
#define QSTR 68   // padded q_s row stride (floats): 272B keeps float4 alignment, avoids bank conflicts

__global__ __launch_bounds__(256) void pass2(const float* __restrict__ queries,
                                             float* __restrict__ out) {
    __shared__ float kv_s[D_ * D_];      // [d][m]
    __shared__ float q_s[TL * QSTR];     // [l][d], padded
    __shared__ float z_s[TL];
    __shared__ float ks_s[D_];

    const int nh   = blockIdx.x;         // 0..31
    const int tile = blockIdx.y;         // 0..63
    const int n = nh >> 3, h = nh & 7;
    const int tid  = threadIdx.x;
    const int lblk = tid >> 4;           // 0..15 -> tokens [lblk*4, lblk*4+3]
    const int mblk = tid & 15;           // 0..15 -> m cols [mblk*4, mblk*4+3]
    const int l0 = tile * TL;

    // Load KV tile (512KB total scratch -> L2-resident across 2048 CTAs)
    #pragma unroll
    for (int r = 0; r < 4; ++r) {
        int f = r * 256 + tid;
        ((float4*)kv_s)[f] = ((const float4*)g_KV[nh])[f];
    }
    if (tid < D_) ks_s[tid] = g_Ksum[nh][tid];

    // Load + featuremap q into [l][d] (padded stride)
    const float* qbase = queries + ((size_t)(n * L_) * H_ + h) * D_;
    {
        int t    = tid >> 2;             // 0..63
        int quad = tid & 3;              // d offset quad*16
        const float4* src = (const float4*)(qbase + (size_t)(l0 + t) * (H_ * D_)) + quad * 4;
        #pragma unroll
        for (int r = 0; r < 4; ++r) {
            float4 qq = src[r];
            qq.x = fmap(qq.x); qq.y = fmap(qq.y); qq.z = fmap(qq.z); qq.w = fmap(qq.w);
            *(float4*)&q_s[t * QSTR + quad * 16 + r * 4] = qq;
        }
    }
    __syncthreads();

    // Normalizer z per token
    if (tid < TL) {
        float s = 0.f;
        #pragma unroll
        for (int d = 0; d < D_; ++d) s += q_s[tid * QSTR + d] * ks_s[d];
        z_s[tid] = 1.f / (s + EPSF);
    }
    __syncthreads();

    // 64x64x64 GEMM: acc[i][j] = sum_d q[l_i][d] * kv[d][m_j]
    float acc[4][4] = {};
    #pragma unroll 4
    for (int d4 = 0; d4 < 16; ++d4) {
        float qr[4][4];   // [i][k]
        float kr[4][4];   // [k][j]
        #pragma unroll
        for (int i = 0; i < 4; ++i) {
            float4 qv = *(float4*)&q_s[(lblk * 4 + i) * QSTR + d4 * 4];
            qr[i][0] = qv.x; qr[i][1] = qv.y; qr[i][2] = qv.z; qr[i][3] = qv.w;
        }
        #pragma unroll
        for (int k = 0; k < 4; ++k) {
            float4 kv = *(float4*)&kv_s[(d4 * 4 + k) * D_ + mblk * 4];
            kr[k][0] = kv.x; kr[k][1] = kv.y; kr[k][2] = kv.z; kr[k][3] = kv.w;
        }
        #pragma unroll
        for (int i = 0; i < 4; ++i)
            #pragma unroll
            for (int j = 0; j < 4; ++j)
                #pragma unroll
                for (int k = 0; k < 4; ++k)
                    acc[i][j] += qr[i][k] * kr[k][j];
    }

    // Scale by z and store
    #pragma unroll
    for (int i = 0; i < 4; ++i) {
        int l = l0 + lblk * 4 + i;
        float z = z_s[lblk * 4 + i];
        float4 o;
        o.x = acc[i][0] * z;
        o.y = acc[i][1] * z;
        o.z = acc[i][2] * z;
        o.w = acc[i][3] * z;
        float* obase = out + (((size_t)(n * L_) + l) * H_ + h) * D_ + mblk * 4;
        *(float4*)obase = o;
    }
}

extern "C" void kernel_launch(void* const* d_in, const int* in_sizes, int n_in,
                              void* d_out, int out_size) {
    const float* q = (const float*)d_in[0];
    const float* k = (const float*)d_in[1];
    const float* v = (const float*)d_in[2];
    float* out = (float*)d_out;
    (void)in_sizes; (void)n_in; (void)out_size;

    zero_kernel<<<(NH * D_ * D_ + 255) / 256, 256>>>();
    pass1<<<dim3(NH, L_ / CHUNK), 256>>>(k, v);
    pass2<<<dim3(NH, L_ / TL), 256>>>(q, out);
}